// round 3
// baseline (speedup 1.0000x reference)
#include <cuda_runtime.h>
#include <math.h>

#define NN 100000
#define NE 1600000

// ---------------- scratch (device globals; no allocation allowed) ----------------
__device__ float g_xW1[NN * 64];
__device__ float g_al_s1[NN * 8];
__device__ float g_al_d1[NN * 8];
__device__ float g_h1[NN * 64];
__device__ float g_xW2[NN * 64];
__device__ float g_al_s2[NN];
__device__ float g_al_d2[NN];
__device__ float g_h2[NN * 64];
__device__ float g_P[NN * 128];
__device__ float g_Q[NN * 128];
__device__ float g_Wla[64 * 128];
__device__ float g_Wlb[64 * 128];
__device__ float g_bP[128];
__device__ float g_bQ[128];
__device__ int   g_deg[NN];
__device__ int   g_cursor[NN];
__device__ int   g_scantmp[NN];
__device__ int   g_rowptr[NN + 1];
__device__ int   g_bsum[128];
__device__ int   g_col[NE];

// ---------------- GEMM: C[nrows,BN] = A[nrows,K] @ B[K,BN] (+bias) ----------------
template <int K, int BN, int TN>
__global__ void __launch_bounds__(256)
k_gemm(const float* __restrict__ A, const float* __restrict__ B, int ldb,
       const float* __restrict__ bias, float* __restrict__ C, int nrows)
{
    constexpr int BM = 64, KC = 16, PAD = 68;
    __shared__ float sB[K * BN];
    __shared__ float sA[KC * PAD];
    const int tid = threadIdx.x;
    const int tx = tid & 15, ty = tid >> 4;
    const int rowBase = blockIdx.x * BM;

    for (int i = tid; i < K * BN; i += 256)
        sB[i] = B[(i / BN) * ldb + (i % BN)];

    float acc[4][TN];
#pragma unroll
    for (int i = 0; i < 4; i++)
#pragma unroll
        for (int j = 0; j < TN; j++) acc[i][j] = 0.f;

    for (int kc = 0; kc < K; kc += KC) {
        __syncthreads();
        {
            int r = tid >> 2;
            int k4 = (tid & 3) << 2;
            int gr = rowBase + r;
            float4 av = make_float4(0.f, 0.f, 0.f, 0.f);
            if (gr < nrows) av = *(const float4*)(A + (long)gr * K + kc + k4);
            sA[(k4 + 0) * PAD + r] = av.x;
            sA[(k4 + 1) * PAD + r] = av.y;
            sA[(k4 + 2) * PAD + r] = av.z;
            sA[(k4 + 3) * PAD + r] = av.w;
        }
        __syncthreads();
#pragma unroll
        for (int kk = 0; kk < KC; kk++) {
            float4 a = *(const float4*)&sA[kk * PAD + 4 * ty];
            const float* bp = &sB[(kc + kk) * BN + 4 * tx];
            float av4[4] = {a.x, a.y, a.z, a.w};
            float bv[TN];
            float4 b0 = *(const float4*)bp;
            bv[0] = b0.x; bv[1] = b0.y; bv[2] = b0.z; bv[3] = b0.w;
            if (TN == 8) {
                float4 b1v = *(const float4*)(bp + 64);
                bv[4] = b1v.x; bv[5] = b1v.y; bv[6] = b1v.z; bv[7] = b1v.w;
            }
#pragma unroll
            for (int i = 0; i < 4; i++)
#pragma unroll
                for (int j = 0; j < TN; j++)
                    acc[i][j] = fmaf(av4[i], bv[j], acc[i][j]);
        }
    }

    float bb[TN];
#pragma unroll
    for (int j = 0; j < TN; j++) {
        int col = (j < 4) ? (4 * tx + j) : (64 + 4 * tx + (j - 4));
        bb[j] = bias ? bias[col] : 0.f;
    }
#pragma unroll
    for (int i = 0; i < 4; i++) {
        int r = rowBase + 4 * ty + i;
        if (r < nrows) {
            float4 o;
            o.x = acc[i][0] + bb[0]; o.y = acc[i][1] + bb[1];
            o.z = acc[i][2] + bb[2]; o.w = acc[i][3] + bb[3];
            *(float4*)(C + (long)r * BN + 4 * tx) = o;
            if (TN == 8) {
                float4 o2;
                o2.x = acc[i][4] + bb[4]; o2.y = acc[i][5] + bb[5];
                o2.z = acc[i][6] + bb[6]; o2.w = acc[i][7] + bb[7];
                *(float4*)(C + (long)r * BN + 64 + 4 * tx) = o2;
            }
        }
    }
}

// ---------------- attention logits: al[n,h] = sum_f xW[n,h*F+f] * a[h,f] ----------------
template <int H>
__global__ void k_al(const float* __restrict__ xW, const float* __restrict__ a_src,
                     const float* __restrict__ a_dst,
                     float* __restrict__ al_s, float* __restrict__ al_d)
{
    int warp = (blockIdx.x * blockDim.x + threadIdx.x) >> 5;
    int lane = threadIdx.x & 31;
    if (warp >= NN) return;
    float v0 = xW[(long)warp * 64 + lane];
    float v1 = xW[(long)warp * 64 + 32 + lane];
    float as0 = v0 * a_src[lane], as1 = v1 * a_src[32 + lane];
    float ad0 = v0 * a_dst[lane], ad1 = v1 * a_dst[32 + lane];
    if (H == 8) {
#pragma unroll
        for (int off = 4; off >= 1; off >>= 1) {
            as0 += __shfl_xor_sync(0xffffffffu, as0, off);
            as1 += __shfl_xor_sync(0xffffffffu, as1, off);
            ad0 += __shfl_xor_sync(0xffffffffu, ad0, off);
            ad1 += __shfl_xor_sync(0xffffffffu, ad1, off);
        }
        if ((lane & 7) == 0) {
            int h = lane >> 3;
            al_s[warp * 8 + h]     = as0;
            al_s[warp * 8 + h + 4] = as1;
            al_d[warp * 8 + h]     = ad0;
            al_d[warp * 8 + h + 4] = ad1;
        }
    } else {
        float s = as0 + as1, d = ad0 + ad1;
#pragma unroll
        for (int off = 16; off >= 1; off >>= 1) {
            s += __shfl_xor_sync(0xffffffffu, s, off);
            d += __shfl_xor_sync(0xffffffffu, d, off);
        }
        if (lane == 0) { al_s[warp] = s; al_d[warp] = d; }
    }
}

// ---------------- CSR build ----------------
__global__ void k_zero2()
{
    int i = blockIdx.x * blockDim.x + threadIdx.x;
    if (i < NN) { g_deg[i] = 0; g_cursor[i] = 0; }
}
__global__ void k_hist(const int* __restrict__ ei)
{
    int e = blockIdx.x * blockDim.x + threadIdx.x;
    if (e < NE) atomicAdd(&g_deg[ei[NE + e]], 1);
}
__global__ void k_scan1()
{
    __shared__ int s[256];
    int tid = threadIdx.x;
    int base = blockIdx.x * 1024 + tid * 4;
    int v0 = (base + 0 < NN) ? g_deg[base + 0] : 0;
    int v1 = (base + 1 < NN) ? g_deg[base + 1] : 0;
    int v2 = (base + 2 < NN) ? g_deg[base + 2] : 0;
    int v3 = (base + 3 < NN) ? g_deg[base + 3] : 0;
    v1 += v0; v2 += v1; v3 += v2;
    int tot = v3;
    s[tid] = tot;
    __syncthreads();
    for (int off = 1; off < 256; off <<= 1) {
        int x = (tid >= off) ? s[tid - off] : 0;
        __syncthreads();
        s[tid] += x;
        __syncthreads();
    }
    int excl = s[tid] - tot;
    if (base + 0 < NN) g_scantmp[base + 0] = v0 + excl;
    if (base + 1 < NN) g_scantmp[base + 1] = v1 + excl;
    if (base + 2 < NN) g_scantmp[base + 2] = v2 + excl;
    if (base + 3 < NN) g_scantmp[base + 3] = v3 + excl;
    if (tid == 255) g_bsum[blockIdx.x] = s[255];
}
__global__ void k_scan2()
{
    __shared__ int s[128];
    int tid = threadIdx.x;
    int nb = (NN + 1023) / 1024;
    int v = (tid < nb) ? g_bsum[tid] : 0;
    s[tid] = v;
    __syncthreads();
    for (int off = 1; off < 128; off <<= 1) {
        int x = (tid >= off) ? s[tid - off] : 0;
        __syncthreads();
        s[tid] += x;
        __syncthreads();
    }
    if (tid < nb) g_bsum[tid] = s[tid] - v;  // exclusive
}
__global__ void k_scan3()
{
    int i = blockIdx.x * blockDim.x + threadIdx.x;
    if (i > NN) return;
    g_rowptr[i] = (i == 0) ? 0 : (g_scantmp[i - 1] + g_bsum[(i - 1) >> 10]);
}
__global__ void k_scatter(const int* __restrict__ ei)
{
    int e = blockIdx.x * blockDim.x + threadIdx.x;
    if (e >= NE) return;
    int dst = ei[NE + e];
    int pos = g_rowptr[dst] + atomicAdd(&g_cursor[dst], 1);
    g_col[pos] = ei[e];
}

// ---------------- GAT layer 1 aggregation (8 heads, online softmax, warp/node) ----------------
__global__ void __launch_bounds__(256)
k_gat1(const float* __restrict__ b1)
{
    int node = (blockIdx.x * blockDim.x + threadIdx.x) >> 5;
    int lane = threadIdx.x & 31;
    if (node >= NN) return;
    int hl = lane & 7;                 // head tracked on this lane (replicated x4)
    float ald = g_al_d1[(long)node * 8 + hl];

    // self-loop initializes the online-softmax state
    float e0 = g_al_s1[(long)node * 8 + hl] + ald;
    e0 = (e0 > 0.f) ? e0 : 0.2f * e0;
    float m = e0, d = 1.f;
    float2 acc = *(const float2*)(g_xW1 + (long)node * 64 + 2 * lane);

    int beg = g_rowptr[node], end = g_rowptr[node + 1];
    for (int i = beg; i < end; i++) {
        int src = g_col[i];
        float ee = g_al_s1[(long)src * 8 + hl] + ald;
        ee = (ee > 0.f) ? ee : 0.2f * ee;
        float mo = m;
        m = fmaxf(m, ee);
        float scale = __expf(mo - m);
        float w = __expf(ee - m);
        d = d * scale + w;
        int owner = lane >> 2;         // head of features {2*lane, 2*lane+1}
        float sb = __shfl_sync(0xffffffffu, scale, owner);
        float wb = __shfl_sync(0xffffffffu, w, owner);
        float2 xv = *(const float2*)(g_xW1 + (long)src * 64 + 2 * lane);
        acc.x = fmaf(wb, xv.x, acc.x * sb);
        acc.y = fmaf(wb, xv.y, acc.y * sb);
    }
    float db = __shfl_sync(0xffffffffu, d, lane >> 2);
    float2 o;
    o.x = acc.x / db + b1[2 * lane];
    o.y = acc.y / db + b1[2 * lane + 1];
    o.x = (o.x > 0.f) ? o.x : expm1f(o.x);
    o.y = (o.y > 0.f) ? o.y : expm1f(o.y);
    *(float2*)(g_h1 + (long)node * 64 + 2 * lane) = o;
}

// ---------------- GAT layer 2 aggregation (1 head) ----------------
__global__ void __launch_bounds__(256)
k_gat2(const float* __restrict__ b2)
{
    int node = (blockIdx.x * blockDim.x + threadIdx.x) >> 5;
    int lane = threadIdx.x & 31;
    if (node >= NN) return;
    float ald = g_al_d2[node];
    float e0 = g_al_s2[node] + ald;
    e0 = (e0 > 0.f) ? e0 : 0.2f * e0;
    float m = e0, d = 1.f;
    float2 acc = *(const float2*)(g_xW2 + (long)node * 64 + 2 * lane);

    int beg = g_rowptr[node], end = g_rowptr[node + 1];
    for (int i = beg; i < end; i++) {
        int src = g_col[i];
        float ee = g_al_s2[src] + ald;
        ee = (ee > 0.f) ? ee : 0.2f * ee;
        float mo = m;
        m = fmaxf(m, ee);
        float scale = __expf(mo - m);
        float w = __expf(ee - m);
        d = d * scale + w;
        float2 xv = *(const float2*)(g_xW2 + (long)src * 64 + 2 * lane);
        acc.x = fmaf(w, xv.x, acc.x * scale);
        acc.y = fmaf(w, xv.y, acc.y * scale);
    }
    float2 o;
    o.x = acc.x / d + b2[2 * lane];
    o.y = acc.y / d + b2[2 * lane + 1];
    o.x = (o.x > 0.f) ? o.x : expm1f(o.x);
    o.y = (o.y > 0.f) ? o.y : expm1f(o.y);
    *(float2*)(g_h2 + (long)node * 64 + 2 * lane) = o;
}

// ---------------- fold lin_W into mlp_W1 halves ----------------
__global__ void k_fold(const float* __restrict__ linW, const float* __restrict__ mW1)
{
    int b = blockIdx.x;           // 128 blocks
    int i = b & 63;
    int off = (b >> 6) ? 64 : 0;
    int c = threadIdx.x;          // 128 threads
    float s = 0.f;
    for (int j = 0; j < 64; j++)
        s = fmaf(linW[i * 64 + j], mW1[(off + j) * 128 + c], s);
    ((b >> 6) ? g_Wlb : g_Wla)[i * 128 + c] = s;
}
__global__ void k_foldbias(const float* __restrict__ linb, const float* __restrict__ mW1)
{
    int t = threadIdx.x;          // 256 threads
    int c = t & 127;
    int off = (t >> 7) ? 64 : 0;
    float s = 0.f;
    for (int j = 0; j < 64; j++)
        s = fmaf(linb[j], mW1[(off + j) * 128 + c], s);
    ((t >> 7) ? g_bQ : g_bP)[c] = s;
}

// ---------------- edge MLP + log_softmax (warp per edge) ----------------
__global__ void __launch_bounds__(256, 2)
k_edge(const int* __restrict__ ei, const float* __restrict__ ea,
       const float* __restrict__ mW1, const float* __restrict__ mb1,
       const float* __restrict__ mW2, const float* __restrict__ mb2,
       float* __restrict__ out)
{
    int lane = threadIdx.x & 31;
    int warp = (blockIdx.x * blockDim.x + threadIdx.x) >> 5;
    int nwarps = (gridDim.x * blockDim.x) >> 5;

    float wc[16][4];
#pragma unroll
    for (int k = 0; k < 16; k++) {
        float4 v = *(const float4*)(mW1 + (long)(128 + k) * 128 + 4 * lane);
        wc[k][0] = v.x; wc[k][1] = v.y; wc[k][2] = v.z; wc[k][3] = v.w;
    }
    float w2a[4], w2b[4], br[4];
#pragma unroll
    for (int u = 0; u < 4; u++) {
        int j = 4 * lane + u;
        w2a[u] = mW2[j * 2 + 0];
        w2b[u] = mW2[j * 2 + 1];
        br[u]  = mb1[j];
    }
    float b20 = mb2[0], b21 = mb2[1];

    for (int e = warp; e < NE; e += nwarps) {
        int src = ei[e];
        int dst = ei[NE + e];
        float eal = (lane < 16) ? ea[(long)e * 16 + lane] : 0.f;
        float4 p = *(const float4*)(g_P + (long)src * 128 + 4 * lane);
        float4 q = *(const float4*)(g_Q + (long)dst * 128 + 4 * lane);
        float h[4] = {p.x + q.x + br[0], p.y + q.y + br[1],
                      p.z + q.z + br[2], p.w + q.w + br[3]};
#pragma unroll
        for (int k = 0; k < 16; k++) {
            float ek = __shfl_sync(0xffffffffu, eal, k);
            h[0] = fmaf(ek, wc[k][0], h[0]);
            h[1] = fmaf(ek, wc[k][1], h[1]);
            h[2] = fmaf(ek, wc[k][2], h[2]);
            h[3] = fmaf(ek, wc[k][3], h[3]);
        }
        float s0 = 0.f, s1 = 0.f;
#pragma unroll
        for (int u = 0; u < 4; u++) {
            float hv = fmaxf(h[u], 0.f);
            s0 = fmaf(hv, w2a[u], s0);
            s1 = fmaf(hv, w2b[u], s1);
        }
#pragma unroll
        for (int off = 16; off >= 1; off >>= 1) {
            s0 += __shfl_xor_sync(0xffffffffu, s0, off);
            s1 += __shfl_xor_sync(0xffffffffu, s1, off);
        }
        if (lane == 0) {
            float o0 = s0 + b20, o1 = s1 + b21;
            float mx = fmaxf(o0, o1), mn = fminf(o0, o1);
            float l = mx + log1pf(expf(mn - mx));
            *(float2*)(out + (long)e * 2) = make_float2(o0 - l, o1 - l);
        }
    }
}

// ---------------- host ----------------
extern "C" void kernel_launch(void* const* d_in, const int* in_sizes, int n_in,
                              void* d_out, int out_size)
{
    (void)in_sizes; (void)n_in; (void)out_size;
    const float* x    = (const float*)d_in[0];
    const int*   ei   = (const int*)d_in[1];
    const float* eatt = (const float*)d_in[2];
    const float* W1   = (const float*)d_in[3];
    const float* as1  = (const float*)d_in[4];
    const float* ad1  = (const float*)d_in[5];
    const float* b1   = (const float*)d_in[6];
    const float* W2   = (const float*)d_in[7];
    const float* as2  = (const float*)d_in[8];
    const float* ad2  = (const float*)d_in[9];
    const float* b2   = (const float*)d_in[10];
    const float* linW = (const float*)d_in[11];
    const float* linb = (const float*)d_in[12];
    const float* mW1  = (const float*)d_in[13];
    const float* mb1  = (const float*)d_in[14];
    const float* mW2  = (const float*)d_in[15];
    const float* mb2  = (const float*)d_in[16];
    float* out = (float*)d_out;

    void *p_xW1, *p_als1, *p_ald1, *p_h1, *p_xW2, *p_als2, *p_ald2, *p_h2;
    void *p_P, *p_Q, *p_Wla, *p_Wlb, *p_bP, *p_bQ;
    cudaGetSymbolAddress(&p_xW1, g_xW1);
    cudaGetSymbolAddress(&p_als1, g_al_s1);
    cudaGetSymbolAddress(&p_ald1, g_al_d1);
    cudaGetSymbolAddress(&p_h1, g_h1);
    cudaGetSymbolAddress(&p_xW2, g_xW2);
    cudaGetSymbolAddress(&p_als2, g_al_s2);
    cudaGetSymbolAddress(&p_ald2, g_al_d2);
    cudaGetSymbolAddress(&p_h2, g_h2);
    cudaGetSymbolAddress(&p_P, g_P);
    cudaGetSymbolAddress(&p_Q, g_Q);
    cudaGetSymbolAddress(&p_Wla, g_Wla);
    cudaGetSymbolAddress(&p_Wlb, g_Wlb);
    cudaGetSymbolAddress(&p_bP, g_bP);
    cudaGetSymbolAddress(&p_bQ, g_bQ);

    const int GEMM_BLOCKS = (NN + 63) / 64;       // 1563
    const int WARP_BLOCKS = (NN + 7) / 8;         // 12500 (warp per node, 8 warps/block)
    const int EDGE_BLOCKS = (NE + 255) / 256;     // 6250

    // CSR build
    k_zero2<<<(NN + 255) / 256, 256>>>();
    k_hist<<<EDGE_BLOCKS, 256>>>(ei);
    k_scan1<<<(NN + 1023) / 1024, 256>>>();
    k_scan2<<<1, 128>>>();
    k_scan3<<<(NN + 1 + 255) / 256, 256>>>();
    k_scatter<<<EDGE_BLOCKS, 256>>>(ei);

    // fold lin into mlp_W1 halves (independent of graph)
    k_fold<<<128, 128>>>(linW, mW1);
    k_foldbias<<<1, 256>>>(linb, mW1);

    // GAT layer 1
    k_gemm<128, 64, 4><<<GEMM_BLOCKS, 256>>>(x, W1, 64, nullptr, (float*)p_xW1, NN);
    k_al<8><<<WARP_BLOCKS, 256>>>((const float*)p_xW1, as1, ad1, (float*)p_als1, (float*)p_ald1);
    k_gat1<<<WARP_BLOCKS, 256>>>(b1);

    // GAT layer 2
    k_gemm<64, 64, 4><<<GEMM_BLOCKS, 256>>>((const float*)p_h1, W2, 64, nullptr, (float*)p_xW2, NN);
    k_al<1><<<WARP_BLOCKS, 256>>>((const float*)p_xW2, as2, ad2, (float*)p_als2, (float*)p_ald2);
    k_gat2<<<WARP_BLOCKS, 256>>>(b2);

    // P = h2 @ (linW@W1a) + lin_b@W1a ; Q likewise for W1b
    k_gemm<64, 128, 8><<<GEMM_BLOCKS, 256>>>((const float*)p_h2, (const float*)p_Wla, 128,
                                             (const float*)p_bP, (float*)p_P, NN);
    k_gemm<64, 128, 8><<<GEMM_BLOCKS, 256>>>((const float*)p_h2, (const float*)p_Wlb, 128,
                                             (const float*)p_bQ, (float*)p_Q, NN);

    // edge MLP + log_softmax
    k_edge<<<2368, 256>>>(ei, eatt, mW1, mb1, mW2, mb2, out);
}